// round 2
// baseline (speedup 1.0000x reference)
#include <cuda_runtime.h>
#include <math.h>

#define BB 256
#define SS 365
#define FD 32
#define FS 27
#define HH 256
#define G3 768

#define OUT_OFF   0
#define HN_OFF    93440
#define CN_OFF    24014080

#define WSTRIDE 260
#define HSM_OFF (48 * WSTRIDE)

__device__ float g_xproj[(size_t)SS * G3 * BB];   // [s][col][b]
__device__ float g_h[2][BB * HH];
__device__ int   g_cnt[8];

__device__ __forceinline__ float sigmoidf_(float x) { return 1.0f / (1.0f + expf(-x)); }

__global__ void reset_kernel() {
    int idx = blockIdx.x * blockDim.x + threadIdx.x;
    if (idx < BB * HH) g_h[0][idx] = 0.0f;
    if (idx < 8) g_cnt[idx] = 0;
}

// grid: S blocks, 256 threads (thread = batch row b)
__global__ void __launch_bounds__(256) xproj_kernel(const float* __restrict__ x_d,
                                                    const float* __restrict__ W_ih) {
    extern __shared__ float sm[];  // [col][d] stride 36
    const int s = blockIdx.x;
    const int tid = threadIdx.x;

    for (int idx = tid; idx < FD * G3; idx += 256) {
        int d = idx / G3, col = idx % G3;
        sm[col * 36 + d] = W_ih[idx];
    }
    __syncthreads();

    float xr[FD];
    const float4* xp4 = reinterpret_cast<const float4*>(x_d + ((size_t)tid * SS + s) * FD);
#pragma unroll
    for (int m = 0; m < 8; m++) {
        float4 v = xp4[m];
        xr[4*m] = v.x; xr[4*m+1] = v.y; xr[4*m+2] = v.z; xr[4*m+3] = v.w;
    }

    float* dst = g_xproj + (size_t)s * G3 * BB + tid;
    for (int col = 0; col < G3; col++) {
        float acc = 0.0f;
#pragma unroll
        for (int m = 0; m < 8; m++) {
            float4 w = *reinterpret_cast<const float4*>(&sm[col * 36 + 4*m]);
            acc = fmaf(xr[4*m], w.x, acc);
            acc = fmaf(xr[4*m+1], w.y, acc);
            acc = fmaf(xr[4*m+2], w.z, acc);
            acc = fmaf(xr[4*m+3], w.w, acc);
        }
        dst[(size_t)col * BB] = acc;
    }
}

// grid = 128: blockIdx = bt*16 + ic. 256 threads.
// warp w -> i pair {ic*16+2w, +1}; lane: ks=lane>>3 (k quarter), bg=lane&7.
__global__ void __launch_bounds__(256, 1) ealstm_kernel(const float* __restrict__ x_s,
                                                        const float* __restrict__ W_hh,
                                                        const float* __restrict__ W_sh,
                                                        const float* __restrict__ bias,
                                                        const float* __restrict__ bias_s,
                                                        float* __restrict__ d_out) {
    extern __shared__ float smem[];
    float* w_sm = smem;             // [48][260]
    float* h_sm = smem + HSM_OFF;   // [32][260]

    const int tid  = threadIdx.x;
    const int warp = tid >> 5;
    const int lane = tid & 31;
    const int ks   = lane >> 3;
    const int bg   = lane & 7;
    const int bt   = blockIdx.x >> 4;
    const int ic   = blockIdx.x & 15;

    for (int idx = tid; idx < 48 * 256; idx += 256) {
        int c = idx % 48, k = idx / 48;
        int gate = c >> 4, il = c & 15;
        w_sm[c * WSTRIDE + k] = W_hh[k * G3 + gate * HH + ic * 16 + il];
    }

    const int b_glob = bt * 32 + bg + 8 * ks;
    const int i0     = ic * 16 + warp * 2;

    float bf[2], bo[2], bgc[2], ig[2], creg[2];
#pragma unroll
    for (int il = 0; il < 2; il++) {
        int i = i0 + il;
        bf[il]  = bias[i];
        bo[il]  = bias[HH + i];
        bgc[il] = bias[2 * HH + i];
        float sum = bias_s[i];
        for (int d = 0; d < FS; d++)
            sum = fmaf(x_s[b_glob * FS + d], W_sh[d * HH + i], sum);
        ig[il] = sigmoidf_(sum);
        creg[il] = 0.0f;
    }
    __syncthreads();

    const int kofs = ks * 64;
    int hrow[4], wrow[6];
#pragma unroll
    for (int j = 0; j < 4; j++) hrow[j] = (bg + 8 * j) * WSTRIDE + kofs;
#pragma unroll
    for (int g = 0; g < 3; g++)
#pragma unroll
        for (int il = 0; il < 2; il++)
            wrow[g * 2 + il] = (g * 16 + warp * 2 + il) * WSTRIDE + kofs;

    for (int s = 0; s < SS; s++) {
        if (tid == 0) {
            volatile int* p = &g_cnt[bt];
            int target = 16 * s;
            while (*p < target) { }
        }
        __syncthreads();

        {
            const float4* hs4 = reinterpret_cast<const float4*>(g_h[s & 1] + (size_t)bt * 32 * HH);
#pragma unroll
            for (int m = 0; m < 8; m++) {
                int f = m * 256 + tid;
                float4 v = __ldcg(hs4 + f);
                int F = f * 4;
                *reinterpret_cast<float4*>(&h_sm[(F >> 8) * WSTRIDE + (F & 255)]) = v;
            }
        }

        float xf[2], xo[2], xg[2];
        {
            const size_t xrow = (size_t)s * G3 * BB + b_glob;
#pragma unroll
            for (int il = 0; il < 2; il++) {
                int i = i0 + il;
                xf[il] = g_xproj[xrow + (size_t)i * BB];
                xo[il] = g_xproj[xrow + (size_t)(HH + i) * BB];
                xg[il] = g_xproj[xrow + (size_t)(2 * HH + i) * BB];
            }
        }
        __syncthreads();

        float acc[4][6];
#pragma unroll
        for (int j = 0; j < 4; j++)
#pragma unroll
            for (int c = 0; c < 6; c++) acc[j][c] = 0.0f;

#pragma unroll 4
        for (int kk = 0; kk < 16; kk++) {
            const int o = kk * 4;
            float4 h4[4];
#pragma unroll
            for (int j = 0; j < 4; j++)
                h4[j] = *reinterpret_cast<const float4*>(&h_sm[hrow[j] + o]);
#pragma unroll
            for (int c = 0; c < 6; c++) {
                float4 w = *reinterpret_cast<const float4*>(&w_sm[wrow[c] + o]);
#pragma unroll
                for (int j = 0; j < 4; j++) {
                    acc[j][c] = fmaf(h4[j].x, w.x, acc[j][c]);
                    acc[j][c] = fmaf(h4[j].y, w.y, acc[j][c]);
                    acc[j][c] = fmaf(h4[j].z, w.z, acc[j][c]);
                    acc[j][c] = fmaf(h4[j].w, w.w, acc[j][c]);
                }
            }
        }

#pragma unroll
        for (int j = 0; j < 4; j++)
#pragma unroll
            for (int c = 0; c < 6; c++) {
                float v = acc[j][c];
                v += __shfl_xor_sync(0xffffffffu, v, 8);
                v += __shfl_xor_sync(0xffffffffu, v, 16);
                acc[j][c] = v;
            }

        float g6[6];
#pragma unroll
        for (int c = 0; c < 6; c++) {
            float v0 = (ks & 1) ? acc[1][c] : acc[0][c];
            float v2 = (ks & 1) ? acc[3][c] : acc[2][c];
            g6[c] = (ks & 2) ? v2 : v0;
        }

        float hv[2], cv[2];
#pragma unroll
        for (int il = 0; il < 2; il++) {
            float f = g6[il]     + bf[il]  + xf[il];
            float o = g6[2 + il] + bo[il]  + xo[il];
            float g = g6[4 + il] + bgc[il] + xg[il];
            float cn = sigmoidf_(f) * creg[il] + ig[il] * tanhf(g);
            float hn = sigmoidf_(o) * tanhf(cn);
            creg[il] = cn;
            hv[il] = hn; cv[il] = cn;
        }

        {
            float2 h2v = make_float2(hv[0], hv[1]);
            float2 c2v = make_float2(cv[0], cv[1]);
            *reinterpret_cast<float2*>(&g_h[(s + 1) & 1][b_glob * HH + i0]) = h2v;
            size_t obase = ((size_t)b_glob * SS + s) * HH + i0;
            *reinterpret_cast<float2*>(&d_out[HN_OFF + obase]) = h2v;
            *reinterpret_cast<float2*>(&d_out[CN_OFF + obase]) = c2v;
        }

        __threadfence();
        __syncthreads();
        if (tid == 0) atomicAdd(&g_cnt[bt], 1);
    }
}

__global__ void __launch_bounds__(256) fc_kernel(const float* __restrict__ W_fc,
                                                 const float* __restrict__ b_fc,
                                                 float* __restrict__ d_out) {
    int gidx = blockIdx.x * 8 + (threadIdx.x >> 5);
    if (gidx >= BB * SS) return;
    int lane = threadIdx.x & 31;

    const float4* h4 = reinterpret_cast<const float4*>(d_out + HN_OFF + (size_t)gidx * HH) + lane * 2;
    const float4* w4 = reinterpret_cast<const float4*>(W_fc) + lane * 2;
    float4 a = h4[0], b = h4[1];
    float4 wa = w4[0], wb = w4[1];
    float sum = a.x * wa.x + a.y * wa.y + a.z * wa.z + a.w * wa.w
              + b.x * wb.x + b.y * wb.y + b.z * wb.z + b.w * wb.w;
#pragma unroll
    for (int off = 16; off > 0; off >>= 1)
        sum += __shfl_xor_sync(0xffffffffu, sum, off);
    if (lane == 0) d_out[OUT_OFF + gidx] = sum + b_fc[0];
}

extern "C" void kernel_launch(void* const* d_in, const int* in_sizes, int n_in,
                              void* d_out, int out_size) {
    const float* x_d    = (const float*)d_in[0];
    const float* x_s    = (const float*)d_in[1];
    const float* W_ih   = (const float*)d_in[2];
    const float* W_hh   = (const float*)d_in[3];
    const float* W_sh   = (const float*)d_in[4];
    const float* bias   = (const float*)d_in[5];
    const float* bias_s = (const float*)d_in[6];
    const float* W_fc   = (const float*)d_in[7];
    const float* b_fc   = (const float*)d_in[8];
    float* out = (float*)d_out;

    const int SMEM_X    = G3 * 36 * sizeof(float);                       // 110592
    const int SMEM_MAIN = (48 * WSTRIDE + 32 * WSTRIDE) * sizeof(float); // 83200

    cudaFuncSetAttribute(xproj_kernel, cudaFuncAttributeMaxDynamicSharedMemorySize, SMEM_X);
    cudaFuncSetAttribute(ealstm_kernel, cudaFuncAttributeMaxDynamicSharedMemorySize, SMEM_MAIN);

    reset_kernel<<<256, 256>>>();
    xproj_kernel<<<SS, 256, SMEM_X>>>(x_d, W_ih);
    ealstm_kernel<<<128, 256, SMEM_MAIN>>>(x_s, W_hh, W_sh, bias, bias_s, out);
    fc_kernel<<<(BB * SS + 7) / 8, 256>>>(W_fc, b_fc, out);
}

// round 3
// speedup vs baseline: 1.0621x; 1.0621x over previous
#include <cuda_runtime.h>
#include <math.h>

#define BB 256
#define SS 365
#define FD 32
#define FS 27
#define HH 256
#define G3 768

#define OUT_OFF   0
#define HN_OFF    93440
#define CN_OFF    24014080

#define WSTRIDE 260
#define HSM_OFF (48 * WSTRIDE)

typedef unsigned long long u64;

__device__ float g_xproj[(size_t)SS * G3 * BB];   // [s][col][b]
__device__ float g_h[2][BB * HH];
__device__ int   g_cnt[8];

__device__ __forceinline__ u64 ffma2(u64 a, u64 b, u64 c) {
    u64 d;
    asm("fma.rn.f32x2 %0, %1, %2, %3;" : "=l"(d) : "l"(a), "l"(b), "l"(c));
    return d;
}
__device__ __forceinline__ float sigm_f(float x) {
    return __fdividef(1.0f, 1.0f + __expf(-x));
}
__device__ __forceinline__ float tanh_f(float x) {
    float t = __expf(2.0f * x);
    return 1.0f - __fdividef(2.0f, t + 1.0f);
}

__global__ void reset_kernel() {
    int idx = blockIdx.x * blockDim.x + threadIdx.x;
    if (idx < BB * HH) g_h[0][idx] = 0.0f;
    if (idx < 8) g_cnt[idx] = 0;
}

// grid: S blocks, 256 threads (thread = batch row b)
__global__ void __launch_bounds__(256) xproj_kernel(const float* __restrict__ x_d,
                                                    const float* __restrict__ W_ih) {
    extern __shared__ float sm[];  // [col][d] stride 36
    const int s = blockIdx.x;
    const int tid = threadIdx.x;

    for (int idx = tid; idx < FD * G3; idx += 256) {
        int d = idx / G3, col = idx % G3;
        sm[col * 36 + d] = W_ih[idx];
    }
    __syncthreads();

    float xr[FD];
    const float4* xp4 = reinterpret_cast<const float4*>(x_d + ((size_t)tid * SS + s) * FD);
#pragma unroll
    for (int m = 0; m < 8; m++) {
        float4 v = xp4[m];
        xr[4*m] = v.x; xr[4*m+1] = v.y; xr[4*m+2] = v.z; xr[4*m+3] = v.w;
    }

    float* dst = g_xproj + (size_t)s * G3 * BB + tid;
    for (int col = 0; col < G3; col++) {
        float acc = 0.0f;
#pragma unroll
        for (int m = 0; m < 8; m++) {
            float4 w = *reinterpret_cast<const float4*>(&sm[col * 36 + 4*m]);
            acc = fmaf(xr[4*m], w.x, acc);
            acc = fmaf(xr[4*m+1], w.y, acc);
            acc = fmaf(xr[4*m+2], w.z, acc);
            acc = fmaf(xr[4*m+3], w.w, acc);
        }
        dst[(size_t)col * BB] = acc;
    }
}

// grid = 128: blockIdx = bt*16 + ic. 256 threads.
// warp w -> i pair {ic*16+2w, +1}; lane: ks=lane>>3 (k quarter), bg=lane&7.
__global__ void __launch_bounds__(256, 1) ealstm_kernel(const float* __restrict__ x_s,
                                                        const float* __restrict__ W_hh,
                                                        const float* __restrict__ W_sh,
                                                        const float* __restrict__ bias,
                                                        const float* __restrict__ bias_s,
                                                        float* __restrict__ d_out) {
    extern __shared__ float smem[];
    float* w_sm = smem;             // [48][260]
    float* h_sm = smem + HSM_OFF;   // [32][260]

    const int tid  = threadIdx.x;
    const int warp = tid >> 5;
    const int lane = tid & 31;
    const int ks   = lane >> 3;
    const int bg   = lane & 7;
    const int bt   = blockIdx.x >> 4;
    const int ic   = blockIdx.x & 15;

    for (int idx = tid; idx < 48 * 256; idx += 256) {
        int c = idx % 48, k = idx / 48;
        int gate = c >> 4, il = c & 15;
        w_sm[c * WSTRIDE + k] = W_hh[k * G3 + gate * HH + ic * 16 + il];
    }

    const int b_glob = bt * 32 + bg + 8 * ks;
    const int i0     = ic * 16 + warp * 2;

    float bf[2], bo[2], bgc[2], ig[2], creg[2];
#pragma unroll
    for (int il = 0; il < 2; il++) {
        int i = i0 + il;
        bf[il]  = bias[i];
        bo[il]  = bias[HH + i];
        bgc[il] = bias[2 * HH + i];
        float sum = bias_s[i];
        for (int d = 0; d < FS; d++)
            sum = fmaf(x_s[b_glob * FS + d], W_sh[d * HH + i], sum);
        // keep precise sigmoid for the static gate (computed once; cheap)
        ig[il] = 1.0f / (1.0f + expf(-sum));
        creg[il] = 0.0f;
    }
    __syncthreads();

    const int kofs = ks * 64;
    int hrow[4], wrow[6];
#pragma unroll
    for (int j = 0; j < 4; j++) hrow[j] = (bg + 8 * j) * WSTRIDE + kofs;
#pragma unroll
    for (int g = 0; g < 3; g++)
#pragma unroll
        for (int il = 0; il < 2; il++)
            wrow[g * 2 + il] = (g * 16 + warp * 2 + il) * WSTRIDE + kofs;

    int* cnt_ptr = &g_cnt[bt];

    for (int s = 0; s < SS; s++) {
        // ---- prefetch x_proj additive terms (independent of h; issued before spin) ----
        float xf[2], xo[2], xg[2];
        {
            const size_t xrow = (size_t)s * G3 * BB + b_glob;
#pragma unroll
            for (int il = 0; il < 2; il++) {
                int i = i0 + il;
                xf[il] = __ldg(&g_xproj[xrow + (size_t)i * BB]);
                xo[il] = __ldg(&g_xproj[xrow + (size_t)(HH + i) * BB]);
                xg[il] = __ldg(&g_xproj[xrow + (size_t)(2 * HH + i) * BB]);
            }
        }

        // ---- wait for h input of step s ----
        if (tid == 0) {
            int target = 16 * s;
            int v;
            do {
                asm volatile("ld.acquire.gpu.global.b32 %0, [%1];"
                             : "=r"(v) : "l"(cnt_ptr) : "memory");
            } while (v < target);
        }
        __syncthreads();

        // ---- load h tile [32 x 256] from global double buffer (coalesced, L2-only) ----
        {
            const float4* hs4 = reinterpret_cast<const float4*>(g_h[s & 1] + (size_t)bt * 32 * HH);
#pragma unroll
            for (int m = 0; m < 8; m++) {
                int f = m * 256 + tid;
                float4 v = __ldcg(hs4 + f);
                int F = f * 4;
                *reinterpret_cast<float4*>(&h_sm[(F >> 8) * WSTRIDE + (F & 255)]) = v;
            }
        }
        __syncthreads();

        // ---- packed f32x2 accumulation over this lane's k quarter ----
        u64 acc[4][6];
#pragma unroll
        for (int j = 0; j < 4; j++)
#pragma unroll
            for (int c = 0; c < 6; c++) acc[j][c] = 0ull;

#pragma unroll 4
        for (int kk = 0; kk < 16; kk++) {
            const int o = kk * 4;
            ulonglong2 h2[4];
#pragma unroll
            for (int j = 0; j < 4; j++)
                h2[j] = *reinterpret_cast<const ulonglong2*>(&h_sm[hrow[j] + o]);
#pragma unroll
            for (int c = 0; c < 6; c++) {
                ulonglong2 w2 = *reinterpret_cast<const ulonglong2*>(&w_sm[wrow[c] + o]);
#pragma unroll
                for (int j = 0; j < 4; j++) {
                    acc[j][c] = ffma2(h2[j].x, w2.x, acc[j][c]);
                    acc[j][c] = ffma2(h2[j].y, w2.y, acc[j][c]);
                }
            }
        }

        // ---- horizontal add + reduce over k quarters ----
        float accs[4][6];
#pragma unroll
        for (int j = 0; j < 4; j++)
#pragma unroll
            for (int c = 0; c < 6; c++) {
                float2 p = *reinterpret_cast<float2*>(&acc[j][c]);
                float v = p.x + p.y;
                v += __shfl_xor_sync(0xffffffffu, v, 8);
                v += __shfl_xor_sync(0xffffffffu, v, 16);
                accs[j][c] = v;
            }

        float g6[6];
#pragma unroll
        for (int c = 0; c < 6; c++) {
            float v0 = (ks & 1) ? accs[1][c] : accs[0][c];
            float v2 = (ks & 1) ? accs[3][c] : accs[2][c];
            g6[c] = (ks & 2) ? v2 : v0;
        }

        // ---- fast gate epilogue ----
        float hv[2], cv[2];
#pragma unroll
        for (int il = 0; il < 2; il++) {
            float f = g6[il]     + bf[il]  + xf[il];
            float o = g6[2 + il] + bo[il]  + xo[il];
            float g = g6[4 + il] + bgc[il] + xg[il];
            float cn = sigm_f(f) * creg[il] + ig[il] * tanh_f(g);
            float hn = sigm_f(o) * tanh_f(cn);
            creg[il] = cn;
            hv[il] = hn; cv[il] = cn;
        }

        // ---- publish h1 (critical path), then release, then cold outputs ----
        float2 h2v = make_float2(hv[0], hv[1]);
        float2 c2v = make_float2(cv[0], cv[1]);
        {
            float2* dst = reinterpret_cast<float2*>(&g_h[(s + 1) & 1][b_glob * HH + i0]);
            __stcg(dst, h2v);
        }
        __syncthreads();
        if (tid == 0) {
            asm volatile("red.release.gpu.global.add.u32 [%0], %1;"
                         :: "l"(cnt_ptr), "r"(1) : "memory");
        }
        {
            size_t obase = ((size_t)b_glob * SS + s) * HH + i0;
            *reinterpret_cast<float2*>(&d_out[HN_OFF + obase]) = h2v;
            *reinterpret_cast<float2*>(&d_out[CN_OFF + obase]) = c2v;
        }
    }
}

__global__ void __launch_bounds__(256) fc_kernel(const float* __restrict__ W_fc,
                                                 const float* __restrict__ b_fc,
                                                 float* __restrict__ d_out) {
    int gidx = blockIdx.x * 8 + (threadIdx.x >> 5);
    if (gidx >= BB * SS) return;
    int lane = threadIdx.x & 31;

    const float4* h4 = reinterpret_cast<const float4*>(d_out + HN_OFF + (size_t)gidx * HH) + lane * 2;
    const float4* w4 = reinterpret_cast<const float4*>(W_fc) + lane * 2;
    float4 a = h4[0], b = h4[1];
    float4 wa = w4[0], wb = w4[1];
    float sum = a.x * wa.x + a.y * wa.y + a.z * wa.z + a.w * wa.w
              + b.x * wb.x + b.y * wb.y + b.z * wb.z + b.w * wb.w;
#pragma unroll
    for (int off = 16; off > 0; off >>= 1)
        sum += __shfl_xor_sync(0xffffffffu, sum, off);
    if (lane == 0) d_out[OUT_OFF + gidx] = sum + b_fc[0];
}

extern "C" void kernel_launch(void* const* d_in, const int* in_sizes, int n_in,
                              void* d_out, int out_size) {
    const float* x_d    = (const float*)d_in[0];
    const float* x_s    = (const float*)d_in[1];
    const float* W_ih   = (const float*)d_in[2];
    const float* W_hh   = (const float*)d_in[3];
    const float* W_sh   = (const float*)d_in[4];
    const float* bias   = (const float*)d_in[5];
    const float* bias_s = (const float*)d_in[6];
    const float* W_fc   = (const float*)d_in[7];
    const float* b_fc   = (const float*)d_in[8];
    float* out = (float*)d_out;

    const int SMEM_X    = G3 * 36 * sizeof(float);                       // 110592
    const int SMEM_MAIN = (48 * WSTRIDE + 32 * WSTRIDE) * sizeof(float); // 83200

    cudaFuncSetAttribute(xproj_kernel, cudaFuncAttributeMaxDynamicSharedMemorySize, SMEM_X);
    cudaFuncSetAttribute(ealstm_kernel, cudaFuncAttributeMaxDynamicSharedMemorySize, SMEM_MAIN);

    reset_kernel<<<256, 256>>>();
    xproj_kernel<<<SS, 256, SMEM_X>>>(x_d, W_ih);
    ealstm_kernel<<<128, 256, SMEM_MAIN>>>(x_s, W_hh, W_sh, bias, bias_s, out);
    fc_kernel<<<(BB * SS + 7) / 8, 256>>>(W_fc, b_fc, out);
}